// round 5
// baseline (speedup 1.0000x reference)
#include <cuda_runtime.h>
#include <cuda_fp16.h>
#include <math.h>

#define NN 80000
#define DD 64
#define EE 1280000

// Scratch (__device__ globals; no allocation allowed in kernel_launch)
__device__ uint4  g_hH[NN * 8];     // h = X@W packed fp16 (8 halves per uint4)
__device__ float4 g_agg4[NN * 16];  // scatter accumulator (fp32)
__device__ uint2  g_H2[NN * 16];    // H = relu(...) packed fp16
__device__ float  g_dinv[NN];
__device__ float  g_gg[NN];
__device__ int    g_cnt[NN];
__device__ int    g_deg[NN];

// ---------------------------------------------------------------------------
__global__ void k_init(int n) {
    int i = blockIdx.x * blockDim.x + threadIdx.x;
    if (i < n * 16) g_agg4[i] = make_float4(0.f, 0.f, 0.f, 0.f);
    if (i < n) {
        g_deg[i] = 1;   // self loop
        g_cnt[i] = 0;
        g_gg[i]  = 0.f;
    }
}

__global__ void k_deg(const int* __restrict__ src, const int* __restrict__ dst, int e) {
    int i = blockIdx.x * blockDim.x + threadIdx.x;
    if (i < e) {
        atomicAdd(&g_deg[dst[i]], 1);
        atomicAdd(&g_cnt[src[i]], 1);
    }
}

__global__ void k_dinv(int n) {
    int i = blockIdx.x * blockDim.x + threadIdx.x;
    if (i < n) g_dinv[i] = rsqrtf((float)g_deg[i]);
}

// ---------------------------------------------------------------------------
// k_gemm: h = X @ W, 8x8 register tile per thread.
// Block = 128 threads covers 128 rows x 64 cols. Per k-step: 8 scalar LDS
// (broadcast across the 8 col-groups) + 2 LDS.128 (W) feed 64 FFMA.
// Xsh layout swizzled: Xsh[row*64 + ((k + row) & 63)] -> stride 64 (no pad),
// read bank = (k + 8*rg + j) % 32: 4 distinct banks x 8-lane broadcast = clean.
// Static smem: 32768 (Xsh) + 16384 (Wsh) = 49152 B = 48KB limit exactly.
// Output written as packed fp16 (8 halves -> uint4).
// ---------------------------------------------------------------------------
__global__ void __launch_bounds__(128) k_gemm(const float* __restrict__ X,
                                              const float* __restrict__ W, int n) {
    __shared__ float  Xsh[128 * 64];
    __shared__ float4 Wsh[64 * 16];

    int tid  = threadIdx.x;
    int base = blockIdx.x * 128;

    // Stage W: 1024 float4, 8 per thread.
    const float4* W4 = (const float4*)W;
#pragma unroll
    for (int j = 0; j < 8; j++) Wsh[tid + 128 * j] = W4[tid + 128 * j];

    // Stage X row-major (swizzled): 2048 float4 (128 rows x 16), coalesced reads.
    const float4* X4 = (const float4*)X;
#pragma unroll
    for (int j = 0; j < 16; j++) {
        int idx = tid + 128 * j;
        int row = idx >> 4;
        int kk  = idx & 15;
        int gr  = base + row;
        float4 v = (gr < n) ? X4[(size_t)gr * 16 + kk]
                            : make_float4(0.f, 0.f, 0.f, 0.f);
        int k0 = kk * 4;
        Xsh[row * 64 + ((k0 + 0 + row) & 63)] = v.x;
        Xsh[row * 64 + ((k0 + 1 + row) & 63)] = v.y;
        Xsh[row * 64 + ((k0 + 2 + row) & 63)] = v.z;
        Xsh[row * 64 + ((k0 + 3 + row) & 63)] = v.w;
    }
    __syncthreads();

    int rg = tid >> 3;   // 0..15 -> rows rg*8 .. rg*8+7
    int cg = tid & 7;    // 0..7  -> cols cg*8 .. cg*8+7

    float acc[8][8];
#pragma unroll
    for (int j = 0; j < 8; j++)
#pragma unroll
        for (int c = 0; c < 8; c++) acc[j][c] = 0.f;

#pragma unroll 4
    for (int k = 0; k < 64; k++) {
        float4 w0 = Wsh[k * 16 + cg * 2];
        float4 w1 = Wsh[k * 16 + cg * 2 + 1];
        float xv[8];
#pragma unroll
        for (int j = 0; j < 8; j++) {
            int row = rg * 8 + j;
            xv[j] = Xsh[row * 64 + ((k + row) & 63)];
        }
#pragma unroll
        for (int j = 0; j < 8; j++) {
            acc[j][0] = fmaf(xv[j], w0.x, acc[j][0]);
            acc[j][1] = fmaf(xv[j], w0.y, acc[j][1]);
            acc[j][2] = fmaf(xv[j], w0.z, acc[j][2]);
            acc[j][3] = fmaf(xv[j], w0.w, acc[j][3]);
            acc[j][4] = fmaf(xv[j], w1.x, acc[j][4]);
            acc[j][5] = fmaf(xv[j], w1.y, acc[j][5]);
            acc[j][6] = fmaf(xv[j], w1.z, acc[j][6]);
            acc[j][7] = fmaf(xv[j], w1.w, acc[j][7]);
        }
    }

#pragma unroll
    for (int j = 0; j < 8; j++) {
        int row = base + rg * 8 + j;
        if (row < n) {
            __half2 h0 = __floats2half2_rn(acc[j][0], acc[j][1]);
            __half2 h1 = __floats2half2_rn(acc[j][2], acc[j][3]);
            __half2 h2 = __floats2half2_rn(acc[j][4], acc[j][5]);
            __half2 h3 = __floats2half2_rn(acc[j][6], acc[j][7]);
            uint4 p;
            p.x = *(unsigned int*)&h0;
            p.y = *(unsigned int*)&h1;
            p.z = *(unsigned int*)&h2;
            p.w = *(unsigned int*)&h3;
            g_hH[row * 8 + cg] = p;
        }
    }
}

// ---------------------------------------------------------------------------
// k_scatter: agg[dst] += h[src] * dinv[src]*dinv[dst]
// 8 lanes/edge; gather fp16 (16B/lane), scale in fp32, two red.v4.f32 per lane.
// ---------------------------------------------------------------------------
__global__ void k_scatter(const int* __restrict__ src, const int* __restrict__ dst, int e) {
    int t = blockIdx.x * blockDim.x + threadIdx.x;
    int ei = t >> 3;
    int lane = t & 7;
    if (ei >= e) return;
    int s = src[ei];
    int d = dst[ei];
    float norm = g_dinv[s] * g_dinv[d];
    uint4 a = __ldg(&g_hH[s * 8 + lane]);
    float2 f0 = __half22float2(*(const __half2*)&a.x);
    float2 f1 = __half22float2(*(const __half2*)&a.y);
    float2 f2 = __half22float2(*(const __half2*)&a.z);
    float2 f3 = __half22float2(*(const __half2*)&a.w);
    float4* addr = &g_agg4[d * 16 + lane * 2];
    asm volatile(
        "red.global.add.v4.f32 [%0], {%1, %2, %3, %4};"
        :: "l"(addr),
           "f"(f0.x * norm), "f"(f0.y * norm), "f"(f1.x * norm), "f"(f1.y * norm)
        : "memory");
    asm volatile(
        "red.global.add.v4.f32 [%0], {%1, %2, %3, %4};"
        :: "l"(addr + 1),
           "f"(f2.x * norm), "f"(f2.y * norm), "f"(f3.x * norm), "f"(f3.y * norm)
        : "memory");
}

// ---------------------------------------------------------------------------
// k_relu: H = relu(agg + h*dinv^2 + b), written as packed fp16.
// ---------------------------------------------------------------------------
__global__ void k_relu(const float* __restrict__ b, int n) {
    int i = blockIdx.x * blockDim.x + threadIdx.x;
    if (i >= n * 16) return;
    int v = i >> 4;
    int c = i & 15;
    float di = g_dinv[v];
    float sl = di * di;
    float4 a = g_agg4[i];
    uint2 hp = ((const uint2*)g_hH)[i];
    float2 h01 = __half22float2(*(const __half2*)&hp.x);
    float2 h23 = __half22float2(*(const __half2*)&hp.y);
    float4 bb = ((const float4*)b)[c];
    float rx = fmaxf(fmaf(h01.x, sl, a.x) + bb.x, 0.f);
    float ry = fmaxf(fmaf(h01.y, sl, a.y) + bb.y, 0.f);
    float rz = fmaxf(fmaf(h23.x, sl, a.z) + bb.z, 0.f);
    float rw = fmaxf(fmaf(h23.y, sl, a.w) + bb.w, 0.f);
    __half2 lo = __floats2half2_rn(rx, ry);
    __half2 hi = __floats2half2_rn(rz, rw);
    uint2 packed;
    packed.x = *(unsigned int*)&lo;
    packed.y = *(unsigned int*)&hi;
    g_H2[i] = packed;
}

// ---------------------------------------------------------------------------
// k_gate: gg[src] += sum_j (H[src,j]-H[dst,j])^2 on fp16 H (fp32 math).
// 8 lanes/edge, each lane owns 8 halves (one uint4 = 16B).
// ---------------------------------------------------------------------------
__global__ void k_gate(const int* __restrict__ src, const int* __restrict__ dst, int e) {
    int t = blockIdx.x * blockDim.x + threadIdx.x;
    int ei = t >> 3;
    int lane = t & 7;
    if (ei >= e) return;
    int r = src[ei];
    int c = dst[ei];
    const uint4* H = (const uint4*)g_H2;   // 8 uint4 per node row
    uint4 a = __ldg(&H[r * 8 + lane]);
    uint4 b = __ldg(&H[c * 8 + lane]);
    const unsigned int* au = (const unsigned int*)&a;
    const unsigned int* bu = (const unsigned int*)&b;
    float s = 0.f;
#pragma unroll
    for (int j = 0; j < 4; j++) {
        float2 fa = __half22float2(*(const __half2*)&au[j]);
        float2 fb = __half22float2(*(const __half2*)&bu[j]);
        float d0 = fa.x - fb.x;
        float d1 = fa.y - fb.y;
        s = fmaf(d0, d0, s);
        s = fmaf(d1, d1, s);
    }
    s += __shfl_xor_sync(0xffffffffu, s, 4);
    s += __shfl_xor_sync(0xffffffffu, s, 2);
    s += __shfl_xor_sync(0xffffffffu, s, 1);
    if (lane == 0) atomicAdd(&g_gg[r], s);
}

__global__ void k_out(float* __restrict__ out, int n) {
    int i = blockIdx.x * blockDim.x + threadIdx.x;
    if (i < n) out[i] = tanhf(g_gg[i] / fmaxf((float)g_cnt[i], 1.f));
}

// ---------------------------------------------------------------------------
extern "C" void kernel_launch(void* const* d_in, const int* in_sizes, int n_in,
                              void* d_out, int out_size) {
    const float* X  = (const float*)d_in[0];
    const int*   ei = (const int*)d_in[1];
    const float* W  = (const float*)d_in[2];
    const float* b  = (const float*)d_in[3];
    float* out = (float*)d_out;

    int n = in_sizes[0] / DD;   // 80000
    int e = in_sizes[1] / 2;    // 1280000
    const int* src = ei;
    const int* dst = ei + e;

    const int T = 256;
    int g_n16 = (n * 16 + T - 1) / T;
    int g_n   = (n + T - 1) / T;
    int g_e   = (e + T - 1) / T;
    int g_rows = (n + 127) / 128;
    long long e8 = (long long)e * 8;
    int g_e8 = (int)((e8 + T - 1) / T);

    k_init<<<g_n16, T>>>(n);
    k_deg<<<g_e, T>>>(src, dst, e);
    k_dinv<<<g_n, T>>>(n);
    k_gemm<<<g_rows, 128>>>(X, W, n);
    k_scatter<<<g_e8, T>>>(src, dst, e);
    k_relu<<<g_n16, T>>>(b, n);
    k_gate<<<g_e8, T>>>(src, dst, e);
    k_out<<<g_n, T>>>(out, n);
}

// round 6
// speedup vs baseline: 1.1476x; 1.1476x over previous
#include <cuda_runtime.h>
#include <cuda_fp16.h>
#include <math.h>

#define NN 80000
#define DD 64
#define EE 1280000

// Scratch (__device__ globals; no allocation allowed in kernel_launch)
__device__ uint2  g_hH[NN * 16];    // h = X@W packed fp16 (4 halves per uint2)
__device__ float4 g_agg4[NN * 16];  // scatter accumulator (fp32)
__device__ uint2  g_H2[NN * 16];    // H = relu(...) packed fp16
__device__ float  g_dinv[NN];
__device__ float  g_gg[NN];
__device__ int    g_cnt[NN];
__device__ int    g_deg[NN];

// ---------------------------------------------------------------------------
__global__ void k_init(int n) {
    int i = blockIdx.x * blockDim.x + threadIdx.x;
    if (i < n * 16) g_agg4[i] = make_float4(0.f, 0.f, 0.f, 0.f);
    if (i < n) {
        g_deg[i] = 1;   // self loop
        g_cnt[i] = 0;
        g_gg[i]  = 0.f;
    }
}

__global__ void k_deg(const int* __restrict__ src, const int* __restrict__ dst, int e) {
    int i = blockIdx.x * blockDim.x + threadIdx.x;
    if (i < e) {
        atomicAdd(&g_deg[dst[i]], 1);
        atomicAdd(&g_cnt[src[i]], 1);
    }
}

__global__ void k_dinv(int n) {
    int i = blockIdx.x * blockDim.x + threadIdx.x;
    if (i < n) g_dinv[i] = rsqrtf((float)g_deg[i]);
}

// ---------------------------------------------------------------------------
// k_gemm: h = X @ W, 4x4 register tile (R2 configuration, measured 27.4us).
// Block = 256 threads covers 64 rows x 64 cols. Thread (rg,cg) computes a
// 4-row x 4-col output tile. X staged transposed (k-major) in smem so 4
// consecutive rows form a float4. Output packed to fp16 (uint2 per c-group).
// ---------------------------------------------------------------------------
#define XS_STRIDE 68   // 64 rows + 4 pad; (68*4) % 16 == 0 keeps float4 alignment
__global__ void __launch_bounds__(256) k_gemm(const float* __restrict__ X,
                                              const float* __restrict__ W, int n) {
    __shared__ float  Xsh[64 * XS_STRIDE];   // Xsh[k][row]
    __shared__ float4 Wsh[64 * 16];          // Wsh[k][cg]

    int tid  = threadIdx.x;
    int base = blockIdx.x * 64;

    // Stage W: 1024 float4, 4 per thread.
    const float4* W4 = (const float4*)W;
#pragma unroll
    for (int i = 0; i < 4; i++) Wsh[tid + 256 * i] = W4[tid + 256 * i];

    // Stage X transposed: each thread loads 4 float4 (row, k-chunk), scatters
    // 4 scalars each into Xsh[k][row].
#pragma unroll
    for (int i = 0; i < 4; i++) {
        int idx = tid + 256 * i;         // 0..1023
        int row = idx & 63;
        int kk  = idx >> 6;              // float4 index along k: 0..15
        int gr  = base + row;
        float4 v = (gr < n) ? ((const float4*)(X + (size_t)gr * 64))[kk]
                            : make_float4(0.f, 0.f, 0.f, 0.f);
        int k0 = kk * 4;
        Xsh[(k0 + 0) * XS_STRIDE + row] = v.x;
        Xsh[(k0 + 1) * XS_STRIDE + row] = v.y;
        Xsh[(k0 + 2) * XS_STRIDE + row] = v.z;
        Xsh[(k0 + 3) * XS_STRIDE + row] = v.w;
    }
    __syncthreads();

    int cg = tid & 15;        // col group (4 cols)
    int rg = tid >> 4;        // row group (4 rows)

    float4 acc0 = make_float4(0.f, 0.f, 0.f, 0.f);
    float4 acc1 = make_float4(0.f, 0.f, 0.f, 0.f);
    float4 acc2 = make_float4(0.f, 0.f, 0.f, 0.f);
    float4 acc3 = make_float4(0.f, 0.f, 0.f, 0.f);

#pragma unroll
    for (int k = 0; k < 64; k++) {
        float4 w  = Wsh[k * 16 + cg];
        float4 xv = *(const float4*)&Xsh[k * XS_STRIDE + rg * 4];
        acc0.x += xv.x * w.x; acc0.y += xv.x * w.y; acc0.z += xv.x * w.z; acc0.w += xv.x * w.w;
        acc1.x += xv.y * w.x; acc1.y += xv.y * w.y; acc1.z += xv.y * w.z; acc1.w += xv.y * w.w;
        acc2.x += xv.z * w.x; acc2.y += xv.z * w.y; acc2.z += xv.z * w.z; acc2.w += xv.z * w.w;
        acc3.x += xv.w * w.x; acc3.y += xv.w * w.y; acc3.z += xv.w * w.z; acc3.w += xv.w * w.w;
    }

    int r0 = base + rg * 4;
#pragma unroll
    for (int j = 0; j < 4; j++) {
        float4 a = (j == 0) ? acc0 : (j == 1) ? acc1 : (j == 2) ? acc2 : acc3;
        int row = r0 + j;
        if (row < n) {
            __half2 lo = __floats2half2_rn(a.x, a.y);
            __half2 hi = __floats2half2_rn(a.z, a.w);
            uint2 p;
            p.x = *(unsigned int*)&lo;
            p.y = *(unsigned int*)&hi;
            g_hH[row * 16 + cg] = p;
        }
    }
}

// ---------------------------------------------------------------------------
// k_scatter: agg[dst] += h[src] * dinv[src]*dinv[dst]
// 16 lanes/edge: each lane gathers 4 halves (uint2, contiguous 128B/edge) and
// issues ONE red.global.add.v4.f32 -> the 16 lanes cover a contiguous 256B
// destination row in a single atomic instruction (fully coalesced sectors).
// ---------------------------------------------------------------------------
__global__ void k_scatter(const int* __restrict__ src, const int* __restrict__ dst, int e) {
    int t = blockIdx.x * blockDim.x + threadIdx.x;
    int ei = t >> 4;
    int lane = t & 15;
    if (ei >= e) return;
    int s = src[ei];
    int d = dst[ei];
    float norm = g_dinv[s] * g_dinv[d];
    uint2 a = __ldg(&g_hH[s * 16 + lane]);
    float2 f0 = __half22float2(*(const __half2*)&a.x);
    float2 f1 = __half22float2(*(const __half2*)&a.y);
    float4* addr = &g_agg4[d * 16 + lane];
    asm volatile(
        "red.global.add.v4.f32 [%0], {%1, %2, %3, %4};"
        :: "l"(addr),
           "f"(f0.x * norm), "f"(f0.y * norm), "f"(f1.x * norm), "f"(f1.y * norm)
        : "memory");
}

// ---------------------------------------------------------------------------
// k_relu: H = relu(agg + h*dinv^2 + b), written as packed fp16.
// ---------------------------------------------------------------------------
__global__ void k_relu(const float* __restrict__ b, int n) {
    int i = blockIdx.x * blockDim.x + threadIdx.x;
    if (i >= n * 16) return;
    int v = i >> 4;
    int c = i & 15;
    float di = g_dinv[v];
    float sl = di * di;
    float4 a = g_agg4[i];
    uint2 hp = g_hH[i];
    float2 h01 = __half22float2(*(const __half2*)&hp.x);
    float2 h23 = __half22float2(*(const __half2*)&hp.y);
    float4 bb = ((const float4*)b)[c];
    float rx = fmaxf(fmaf(h01.x, sl, a.x) + bb.x, 0.f);
    float ry = fmaxf(fmaf(h01.y, sl, a.y) + bb.y, 0.f);
    float rz = fmaxf(fmaf(h23.x, sl, a.z) + bb.z, 0.f);
    float rw = fmaxf(fmaf(h23.y, sl, a.w) + bb.w, 0.f);
    __half2 lo = __floats2half2_rn(rx, ry);
    __half2 hi = __floats2half2_rn(rz, rw);
    uint2 packed;
    packed.x = *(unsigned int*)&lo;
    packed.y = *(unsigned int*)&hi;
    g_H2[i] = packed;
}

// ---------------------------------------------------------------------------
// k_gate: gg[src] += sum_j (H[src,j]-H[dst,j])^2 on fp16 H (fp32 math).
// 8 lanes/edge, each lane owns 8 halves (one uint4 = 16B).
// ---------------------------------------------------------------------------
__global__ void k_gate(const int* __restrict__ src, const int* __restrict__ dst, int e) {
    int t = blockIdx.x * blockDim.x + threadIdx.x;
    int ei = t >> 3;
    int lane = t & 7;
    if (ei >= e) return;
    int r = src[ei];
    int c = dst[ei];
    const uint4* H = (const uint4*)g_H2;   // 8 uint4 per node row
    uint4 a = __ldg(&H[r * 8 + lane]);
    uint4 b = __ldg(&H[c * 8 + lane]);
    const unsigned int* au = (const unsigned int*)&a;
    const unsigned int* bu = (const unsigned int*)&b;
    float s = 0.f;
#pragma unroll
    for (int j = 0; j < 4; j++) {
        float2 fa = __half22float2(*(const __half2*)&au[j]);
        float2 fb = __half22float2(*(const __half2*)&bu[j]);
        float d0 = fa.x - fb.x;
        float d1 = fa.y - fb.y;
        s = fmaf(d0, d0, s);
        s = fmaf(d1, d1, s);
    }
    s += __shfl_xor_sync(0xffffffffu, s, 4);
    s += __shfl_xor_sync(0xffffffffu, s, 2);
    s += __shfl_xor_sync(0xffffffffu, s, 1);
    if (lane == 0) atomicAdd(&g_gg[r], s);
}

__global__ void k_out(float* __restrict__ out, int n) {
    int i = blockIdx.x * blockDim.x + threadIdx.x;
    if (i < n) out[i] = tanhf(g_gg[i] / fmaxf((float)g_cnt[i], 1.f));
}

// ---------------------------------------------------------------------------
extern "C" void kernel_launch(void* const* d_in, const int* in_sizes, int n_in,
                              void* d_out, int out_size) {
    const float* X  = (const float*)d_in[0];
    const int*   ei = (const int*)d_in[1];
    const float* W  = (const float*)d_in[2];
    const float* b  = (const float*)d_in[3];
    float* out = (float*)d_out;

    int n = in_sizes[0] / DD;   // 80000
    int e = in_sizes[1] / 2;    // 1280000
    const int* src = ei;
    const int* dst = ei + e;

    const int T = 256;
    int g_n16 = (n * 16 + T - 1) / T;
    int g_n   = (n + T - 1) / T;
    int g_e   = (e + T - 1) / T;
    int g_rows = (n + 63) / 64;
    long long e16 = (long long)e * 16;
    int g_e16 = (int)((e16 + T - 1) / T);
    long long e8 = (long long)e * 8;
    int g_e8 = (int)((e8 + T - 1) / T);

    k_init<<<g_n16, T>>>(n);
    k_deg<<<g_e, T>>>(src, dst, e);
    k_dinv<<<g_n, T>>>(n);
    k_gemm<<<g_rows, T>>>(X, W, n);
    k_scatter<<<g_e16, T>>>(src, dst, e);
    k_relu<<<g_n16, T>>>(b, n);
    k_gate<<<g_e8, T>>>(src, dst, e);
    k_out<<<g_n, T>>>(out, n);
}

// round 7
// speedup vs baseline: 1.3266x; 1.1560x over previous
#include <cuda_runtime.h>
#include <cuda_fp16.h>
#include <math.h>

#define NN 80000
#define DD 64
#define EE 1280000
#define NB ((NN + 255) / 256)   // scan blocks = 313

// Scratch (__device__ globals; no allocation allowed in kernel_launch)
__device__ uint2 g_hH[NN * 16];   // h = X@W packed fp16 (row = 32 uints = 64 halves)
__device__ uint2 g_H2[NN * 16];   // H = relu(...) packed fp16
__device__ float g_dinv[NN];
__device__ float g_gg[NN];
__device__ int   g_cnt[NN];       // out-degree (gate denominator)
__device__ int   g_deg[NN];       // in-degree (no self loop)
__device__ int   g_start[NN];     // CSR row start
__device__ int   g_cursor[NN];    // build cursor
__device__ int   g_adj[EE];       // CSR: src indices bucketed by dst
__device__ int   g_bsum[NB];      // scan block sums

// ---------------------------------------------------------------------------
__global__ void k_init(int n) {
    int i = blockIdx.x * blockDim.x + threadIdx.x;
    if (i < n) {
        g_deg[i] = 0;
        g_cnt[i] = 0;
        g_gg[i]  = 0.f;
    }
}

__global__ void k_deg(const int* __restrict__ src, const int* __restrict__ dst, int e) {
    int i = blockIdx.x * blockDim.x + threadIdx.x;
    if (i < e) {
        atomicAdd(&g_deg[dst[i]], 1);
        atomicAdd(&g_cnt[src[i]], 1);
    }
}

// ---------------------------------------------------------------------------
// 3-pass exclusive scan of g_deg -> g_start (CSR offsets).
// ---------------------------------------------------------------------------
__global__ void k_scan1(int n) {   // per-block exclusive scan + block totals
    __shared__ int sd[256];
    int i = blockIdx.x * 256 + threadIdx.x;
    int v = (i < n) ? g_deg[i] : 0;
    sd[threadIdx.x] = v;
    __syncthreads();
    int acc = v;
#pragma unroll
    for (int off = 1; off < 256; off <<= 1) {
        int t = (threadIdx.x >= off) ? sd[threadIdx.x - off] : 0;
        __syncthreads();
        acc += t;
        sd[threadIdx.x] = acc;
        __syncthreads();
    }
    if (i < n) g_start[i] = acc - v;            // exclusive within block
    if (threadIdx.x == 255) g_bsum[blockIdx.x] = acc;  // block total
}

__global__ void k_scan2() {        // exclusive scan of block totals (one block)
    __shared__ int sd[512];
    int i = threadIdx.x;
    int v = (i < NB) ? g_bsum[i] : 0;
    sd[i] = v;
    __syncthreads();
    int acc = v;
#pragma unroll
    for (int off = 1; off < 512; off <<= 1) {
        int t = (i >= off) ? sd[i - off] : 0;
        __syncthreads();
        acc += t;
        sd[i] = acc;
        __syncthreads();
    }
    if (i < NB) g_bsum[i] = acc - v;            // exclusive
}

__global__ void k_scan3(int n) {   // add block offsets; init cursor; dinv
    int i = blockIdx.x * blockDim.x + threadIdx.x;
    if (i < n) {
        int s = g_start[i] + g_bsum[blockIdx.x * 256 / 256 == 0 ? 0 : 0];  // placeholder
        s = g_start[i] + g_bsum[i >> 8];
        g_start[i]  = s;
        g_cursor[i] = s;
        g_dinv[i]   = rsqrtf((float)(g_deg[i] + 1));   // +1 self loop
    }
}

__global__ void k_build(const int* __restrict__ src, const int* __restrict__ dst, int e) {
    int i = blockIdx.x * blockDim.x + threadIdx.x;
    if (i < e) {
        int pos = atomicAdd(&g_cursor[dst[i]], 1);
        g_adj[pos] = src[i];
    }
}

// ---------------------------------------------------------------------------
// k_gemm: h = X @ W, 4x4 register tile (measured 27us). fp16 packed output.
// ---------------------------------------------------------------------------
#define XS_STRIDE 68
__global__ void __launch_bounds__(256) k_gemm(const float* __restrict__ X,
                                              const float* __restrict__ W, int n) {
    __shared__ float  Xsh[64 * XS_STRIDE];   // Xsh[k][row]
    __shared__ float4 Wsh[64 * 16];          // Wsh[k][cg]

    int tid  = threadIdx.x;
    int base = blockIdx.x * 64;

    const float4* W4 = (const float4*)W;
#pragma unroll
    for (int i = 0; i < 4; i++) Wsh[tid + 256 * i] = W4[tid + 256 * i];

#pragma unroll
    for (int i = 0; i < 4; i++) {
        int idx = tid + 256 * i;
        int row = idx & 63;
        int kk  = idx >> 6;
        int gr  = base + row;
        float4 v = (gr < n) ? ((const float4*)(X + (size_t)gr * 64))[kk]
                            : make_float4(0.f, 0.f, 0.f, 0.f);
        int k0 = kk * 4;
        Xsh[(k0 + 0) * XS_STRIDE + row] = v.x;
        Xsh[(k0 + 1) * XS_STRIDE + row] = v.y;
        Xsh[(k0 + 2) * XS_STRIDE + row] = v.z;
        Xsh[(k0 + 3) * XS_STRIDE + row] = v.w;
    }
    __syncthreads();

    int cg = tid & 15;
    int rg = tid >> 4;

    float4 acc0 = make_float4(0.f, 0.f, 0.f, 0.f);
    float4 acc1 = make_float4(0.f, 0.f, 0.f, 0.f);
    float4 acc2 = make_float4(0.f, 0.f, 0.f, 0.f);
    float4 acc3 = make_float4(0.f, 0.f, 0.f, 0.f);

#pragma unroll
    for (int k = 0; k < 64; k++) {
        float4 w  = Wsh[k * 16 + cg];
        float4 xv = *(const float4*)&Xsh[k * XS_STRIDE + rg * 4];
        acc0.x += xv.x * w.x; acc0.y += xv.x * w.y; acc0.z += xv.x * w.z; acc0.w += xv.x * w.w;
        acc1.x += xv.y * w.x; acc1.y += xv.y * w.y; acc1.z += xv.y * w.z; acc1.w += xv.y * w.w;
        acc2.x += xv.z * w.x; acc2.y += xv.z * w.y; acc2.z += xv.z * w.z; acc2.w += xv.z * w.w;
        acc3.x += xv.w * w.x; acc3.y += xv.w * w.y; acc3.z += xv.w * w.z; acc3.w += xv.w * w.w;
    }

    int r0 = base + rg * 4;
#pragma unroll
    for (int j = 0; j < 4; j++) {
        float4 a = (j == 0) ? acc0 : (j == 1) ? acc1 : (j == 2) ? acc2 : acc3;
        int row = r0 + j;
        if (row < n) {
            __half2 lo = __floats2half2_rn(a.x, a.y);
            __half2 hi = __floats2half2_rn(a.z, a.w);
            uint2 p;
            p.x = *(unsigned int*)&lo;
            p.y = *(unsigned int*)&hi;
            g_hH[row * 16 + cg] = p;
        }
    }
}

// ---------------------------------------------------------------------------
// k_agg: warp per node. Register-accumulated CSR gather; fuses self-loop,
// bias, relu, fp16 pack of H. No atomics, no agg array.
// Lane l owns feature columns 2l, 2l+1 (one half2 / float2).
// ---------------------------------------------------------------------------
__global__ void __launch_bounds__(256) k_agg(const float* __restrict__ b, int n) {
    int warp = (blockIdx.x * blockDim.x + threadIdx.x) >> 5;
    int lane = threadIdx.x & 31;
    if (warp >= n) return;
    int d = warp;

    const unsigned int* h2 = (const unsigned int*)g_hH;  // 32 uints per row
    float dinv_d = g_dinv[d];

    int s0  = g_start[d];
    int cnt = g_deg[d];
    float2 acc = make_float2(0.f, 0.f);

    for (int j = 0; j < cnt; j++) {
        int s = g_adj[s0 + j];                 // broadcast within warp
        float norm = g_dinv[s] * dinv_d;       // broadcast (L1 hit)
        float2 hv = __half22float2(*(const __half2*)&h2[s * 32 + lane]);
        acc.x = fmaf(hv.x, norm, acc.x);
        acc.y = fmaf(hv.y, norm, acc.y);
    }

    // self loop: + h[d] * dinv_d^2, then bias, relu
    float sl = dinv_d * dinv_d;
    float2 hd = __half22float2(*(const __half2*)&h2[d * 32 + lane]);
    float2 bb = ((const float2*)b)[lane];
    float rx = fmaxf(fmaf(hd.x, sl, acc.x) + bb.x, 0.f);
    float ry = fmaxf(fmaf(hd.y, sl, acc.y) + bb.y, 0.f);
    __half2 hh = __floats2half2_rn(rx, ry);
    ((unsigned int*)g_H2)[d * 32 + lane] = *(unsigned int*)&hh;
}

// ---------------------------------------------------------------------------
// k_gate: gg[src] += sum_j (H[src,j]-H[dst,j])^2 on fp16 H (fp32 math).
// 8 lanes/edge, each lane owns one uint4 (16B).
// ---------------------------------------------------------------------------
__global__ void k_gate(const int* __restrict__ src, const int* __restrict__ dst, int e) {
    int t = blockIdx.x * blockDim.x + threadIdx.x;
    int ei = t >> 3;
    int lane = t & 7;
    if (ei >= e) return;
    int r = src[ei];
    int c = dst[ei];
    const uint4* H = (const uint4*)g_H2;
    uint4 a = __ldg(&H[r * 8 + lane]);
    uint4 b = __ldg(&H[c * 8 + lane]);
    const unsigned int* au = (const unsigned int*)&a;
    const unsigned int* bu = (const unsigned int*)&b;
    float s = 0.f;
#pragma unroll
    for (int j = 0; j < 4; j++) {
        float2 fa = __half22float2(*(const __half2*)&au[j]);
        float2 fb = __half22float2(*(const __half2*)&bu[j]);
        float d0 = fa.x - fb.x;
        float d1 = fa.y - fb.y;
        s = fmaf(d0, d0, s);
        s = fmaf(d1, d1, s);
    }
    s += __shfl_xor_sync(0xffffffffu, s, 4);
    s += __shfl_xor_sync(0xffffffffu, s, 2);
    s += __shfl_xor_sync(0xffffffffu, s, 1);
    if (lane == 0) atomicAdd(&g_gg[r], s);
}

__global__ void k_out(float* __restrict__ out, int n) {
    int i = blockIdx.x * blockDim.x + threadIdx.x;
    if (i < n) out[i] = tanhf(g_gg[i] / fmaxf((float)g_cnt[i], 1.f));
}

// ---------------------------------------------------------------------------
extern "C" void kernel_launch(void* const* d_in, const int* in_sizes, int n_in,
                              void* d_out, int out_size) {
    const float* X  = (const float*)d_in[0];
    const int*   ei = (const int*)d_in[1];
    const float* W  = (const float*)d_in[2];
    const float* b  = (const float*)d_in[3];
    float* out = (float*)d_out;

    int n = in_sizes[0] / DD;   // 80000
    int e = in_sizes[1] / 2;    // 1280000
    const int* src = ei;
    const int* dst = ei + e;

    const int T = 256;
    int g_n    = (n + T - 1) / T;
    int g_e    = (e + T - 1) / T;
    int g_rows = (n + 63) / 64;
    int g_warp = (n * 32 + T - 1) / T;
    long long e8 = (long long)e * 8;
    int g_e8 = (int)((e8 + T - 1) / T);

    k_init <<<g_n, T>>>(n);
    k_deg  <<<g_e, T>>>(src, dst, e);
    k_scan1<<<NB, 256>>>(n);
    k_scan2<<<1, 512>>>();
    k_scan3<<<g_n, T>>>(n);
    k_build<<<g_e, T>>>(src, dst, e);
    k_gemm <<<g_rows, T>>>(X, W, n);
    k_agg  <<<g_warp, T>>>(b, n);
    k_gate <<<g_e8, T>>>(src, dst, e);
    k_out  <<<g_n, T>>>(out, n);
}